// round 2
// baseline (speedup 1.0000x reference)
#include <cuda_runtime.h>

// ---------------------------------------------------------------------------
// WaveNet-like 33-stage dilated gated conv stack x3 submodules + PinSage head.
// fp32 with packed f32x2 FMAs (Blackwell fma.rn.f32x2) and HW tanh.approx.
// State buffers live in __device__ globals (L2-resident, ~6MB each).
// ---------------------------------------------------------------------------

#define S3   3
#define BB   8
#define CH   16      // residual channels
#define GC   32      // gate channels
#define LL   4096
#define RR   24      // S3*BB rows
#define TILE 256     // positions per gate-CTA

typedef unsigned long long ull;

__device__ __forceinline__ ull pk(float a, float b) {
    ull r; asm("mov.b64 %0, {%1,%2};" : "=l"(r) : "f"(a), "f"(b)); return r;
}
__device__ __forceinline__ ull dup2(float a) {
    ull r; asm("mov.b64 %0, {%1,%1};" : "=l"(r) : "f"(a)); return r;
}
__device__ __forceinline__ void upk(ull v, float &a, float &b) {
    asm("mov.b64 {%0,%1}, %2;" : "=f"(a), "=f"(b) : "l"(v));
}
__device__ __forceinline__ ull f2fma(ull a, ull b, ull c) {
    ull r; asm("fma.rn.f32x2 %0, %1, %2, %3;" : "=l"(r) : "l"(a), "l"(b), "l"(c)); return r;
}
__device__ __forceinline__ float tanhap(float x) {
    float r; asm("tanh.approx.f32 %0, %1;" : "=f"(r) : "f"(x)); return r;
}
__device__ __forceinline__ float sigap(float x) {   // sigmoid(x) = 0.5*tanh(0.5x)+0.5
    return fmaf(tanhap(x * 0.5f), 0.5f, 0.5f);
}

// State buffers: [row=(s*8+b)][c][l]
__device__ float g_X [RR * CH * LL];
__device__ float g_SK[RR * CH * LL];
__device__ float g_H [RR * CH * LL];

// ---------------------------------------------------------------------------
// Stage-0 pointwise conv: h = relu(w[o]*x_in + b[o]),  x_in layout [B,L,3]
// ---------------------------------------------------------------------------
__global__ void __launch_bounds__(128) k_first(const float* __restrict__ xin,
                                               const float* __restrict__ w,
                                               const float* __restrict__ b) {
    int row = blockIdx.y, s = row >> 3, bb = row & 7;
    int p0 = blockIdx.x * 512 + threadIdx.x * 4;
    float xv[4];
#pragma unroll
    for (int j = 0; j < 4; j++) xv[j] = xin[(bb * LL + p0 + j) * 3 + s];
    const float* ws = w + s * 16;
    const float* bs = b + s * 16;
    float* H = g_H + row * CH * LL;
#pragma unroll
    for (int o = 0; o < 16; o++) {
        float wo = ws[o], bo = bs[o];
#pragma unroll
        for (int j = 0; j < 4; j++)
            H[o * LL + p0 + j] = fmaxf(fmaf(wo, xv[j], bo), 0.f);
    }
}

// ---------------------------------------------------------------------------
// Pointwise conv stages i>=1: h = relu(W1[16x16] x + b1)
// ---------------------------------------------------------------------------
__global__ void __launch_bounds__(128) k_point(const float* __restrict__ wg,
                                               const float* __restrict__ bg,
                                               int i) {
    __shared__ float ws[256];
    __shared__ float bs[16];
    int row = blockIdx.y, s = row >> 3;
    const float* wsrc = wg + (s * 32 + (i - 1)) * 256;
    const float* bsrc = bg + (s * 32 + (i - 1)) * 16;
    int tid = threadIdx.x;
    for (int idx = tid; idx < 256; idx += 128) ws[idx] = wsrc[idx];
    if (tid < 16) bs[tid] = bsrc[tid];
    __syncthreads();

    const float* X = g_X + row * CH * LL;
    float* H = g_H + row * CH * LL;
    int p0 = blockIdx.x * 512 + tid * 4;

    ull acc[16][2];
#pragma unroll
    for (int o = 0; o < 16; o++) { ull bv = dup2(bs[o]); acc[o][0] = bv; acc[o][1] = bv; }

#pragma unroll 4
    for (int c = 0; c < 16; c++) {
        float2 x0 = *reinterpret_cast<const float2*>(X + c * LL + p0);
        float2 x1 = *reinterpret_cast<const float2*>(X + c * LL + p0 + 2);
        ull xa = pk(x0.x, x0.y), xb = pk(x1.x, x1.y);
#pragma unroll
        for (int o = 0; o < 16; o++) {
            ull wd = dup2(ws[o * 16 + c]);
            acc[o][0] = f2fma(xa, wd, acc[o][0]);
            acc[o][1] = f2fma(xb, wd, acc[o][1]);
        }
    }
#pragma unroll
    for (int o = 0; o < 16; o++) {
        float a, b2, c2, d2;
        upk(acc[o][0], a, b2); upk(acc[o][1], c2, d2);
        *reinterpret_cast<float2*>(H + o * LL + p0)     = make_float2(fmaxf(a, 0.f),  fmaxf(b2, 0.f));
        *reinterpret_cast<float2*>(H + o * LL + p0 + 2) = make_float2(fmaxf(c2, 0.f), fmaxf(d2, 0.f));
    }
}

// ---------------------------------------------------------------------------
// Gate kernel: dilated k=2 convs f,g -> z = tanh(f)*sig(g) -> z2 = relu(W2 z)
//              X = h + z2 ; SK (+)= z2
// CTA = 128 threads: 8 oc-quads x 16 position-groups; 16 positions/thread.
// h tile (+halo d) staged in smem; weights in smem.
// ---------------------------------------------------------------------------
template <bool FIRST>
__global__ void __launch_bounds__(128) k_gate(const float* __restrict__ cfw,
                                              const float* __restrict__ cfb,
                                              const float* __restrict__ cgw,
                                              const float* __restrict__ cgb,
                                              const float* __restrict__ c2w,
                                              const float* __restrict__ c2b,
                                              int i, int d) {
    extern __shared__ float sm[];
    float* wf_s = sm;                 // 1024
    float* wg_s = sm + 1024;          // 1024
    float* w2_s = sm + 2048;          // 512
    float* bf_s = sm + 2560;          // 32
    float* bg_s = sm + 2592;          // 32
    float* b2_s = sm + 2624;          // 16
    float* z_s  = sm + 2640;          // 32*TILE = 8192
    float* h_s  = sm + 2640 + GC * TILE;  // 16*(TILE+d)

    int tid = threadIdx.x;
    int row = blockIdx.y, s = row >> 3;
    int tile0 = blockIdx.x * TILE;
    int a = d >> 1;
    int HS = TILE + d;

    {   // stage weights -> smem
        int wb = s * 33 + i;
        const float* fsrc = cfw + wb * 1024;
        const float* gsrc = cgw + wb * 1024;
        for (int idx = tid; idx < 1024; idx += 128) { wf_s[idx] = fsrc[idx]; wg_s[idx] = gsrc[idx]; }
        const float* w2src = c2w + wb * 512;
        for (int idx = tid; idx < 512; idx += 128) w2_s[idx] = w2src[idx];
        if (tid < 32) { bf_s[tid] = cfb[wb * 32 + tid]; bg_s[tid] = cgb[wb * 32 + tid]; }
        if (tid < 16) b2_s[tid] = c2b[wb * 16 + tid];
    }
    {   // h tile + halo -> smem (zero padded outside [0,L))
        const float* Hg = g_H + row * CH * LL;
        int start = tile0 - a;
#pragma unroll
        for (int c = 0; c < 16; c++) {
            const float* hc = Hg + c * LL;
            float* dst = h_s + c * HS;
            for (int po = tid; po < HS; po += 128) {
                int pos = start + po;
                dst[po] = (pos >= 0 && pos < LL) ? hc[pos] : 0.f;
            }
        }
    }
    __syncthreads();

    int q = tid >> 4, pg = tid & 15;
    int base = pg * 2;
    int ocb = q * 4;

    // -------- main GEMV: f,g accumulators (4 oc x 8 packed pairs each) --------
    ull fA[4][8], gA[4][8];
#pragma unroll
    for (int ii = 0; ii < 4; ii++) {
        ull fb2 = dup2(bf_s[ocb + ii]), gb2 = dup2(bg_s[ocb + ii]);
#pragma unroll
        for (int j = 0; j < 8; j++) { fA[ii][j] = fb2; gA[ii][j] = gb2; }
    }
#pragma unroll 2
    for (int c = 0; c < 16; c++) {
        const float* hp = h_s + c * HS + base;   // tap 0  (pos - a)
        const float* hq = hp + d;                // tap 1  (pos + d - a)
        ull hl[8], hr[8];
#pragma unroll
        for (int j = 0; j < 8; j++) {
            hl[j] = pk(hp[32 * j], hp[32 * j + 1]);
            hr[j] = pk(hq[32 * j], hq[32 * j + 1]);
        }
#pragma unroll
        for (int ii = 0; ii < 4; ii++) {
            int wo = ((ocb + ii) * 16 + c) * 2;
            ull wf0 = dup2(wf_s[wo]), wf1 = dup2(wf_s[wo + 1]);
            ull wg0 = dup2(wg_s[wo]), wg1 = dup2(wg_s[wo + 1]);
#pragma unroll
            for (int j = 0; j < 8; j++) {
                fA[ii][j] = f2fma(hl[j], wf0, fA[ii][j]);
                fA[ii][j] = f2fma(hr[j], wf1, fA[ii][j]);
                gA[ii][j] = f2fma(hl[j], wg0, gA[ii][j]);
                gA[ii][j] = f2fma(hr[j], wg1, gA[ii][j]);
            }
        }
    }

    // -------- activations -> z smem --------
#pragma unroll
    for (int ii = 0; ii < 4; ii++) {
        int oc = ocb + ii;
#pragma unroll
        for (int j = 0; j < 8; j++) {
            float f0, f1, g0, g1;
            upk(fA[ii][j], f0, f1); upk(gA[ii][j], g0, g1);
            int lp = base + 32 * j;
            z_s[oc * TILE + lp]     = tanhap(f0) * sigap(g0);
            z_s[oc * TILE + lp + 1] = tanhap(f1) * sigap(g1);
        }
    }
    __syncthreads();

    // -------- z2 = relu(W2 z + b2); X = h + z2; SK (+)= z2 --------
    int o0 = q * 2;
    ull acc[2][8];
#pragma unroll
    for (int oi = 0; oi < 2; oi++) {
        ull bv = dup2(b2_s[o0 + oi]);
#pragma unroll
        for (int j = 0; j < 8; j++) acc[oi][j] = bv;
    }
#pragma unroll 4
    for (int k = 0; k < 32; k++) {
        ull w0 = dup2(w2_s[o0 * 32 + k]);
        ull w1 = dup2(w2_s[(o0 + 1) * 32 + k]);
        const float* zp = z_s + k * TILE + base;
#pragma unroll
        for (int j = 0; j < 8; j++) {
            float2 zz = *reinterpret_cast<const float2*>(zp + 32 * j);
            ull zv = pk(zz.x, zz.y);
            acc[0][j] = f2fma(zv, w0, acc[0][j]);
            acc[1][j] = f2fma(zv, w1, acc[1][j]);
        }
    }
    float* Xg  = g_X  + row * CH * LL;
    float* SKg = g_SK + row * CH * LL;
#pragma unroll
    for (int oi = 0; oi < 2; oi++) {
        int o = o0 + oi;
        const float* hc = h_s + o * HS + a + base;  // center h(pos)
        float* xo = Xg  + o * LL + tile0 + base;
        float* so = SKg + o * LL + tile0 + base;
#pragma unroll
        for (int j = 0; j < 8; j++) {
            float r0, r1; upk(acc[oi][j], r0, r1);
            r0 = fmaxf(r0, 0.f); r1 = fmaxf(r1, 0.f);
            int lp = 32 * j;
            *reinterpret_cast<float2*>(xo + lp) = make_float2(hc[lp] + r0, hc[lp + 1] + r1);
            if (FIRST) {
                *reinterpret_cast<float2*>(so + lp) = make_float2(r0, r1);
            } else {
                float2 old = *reinterpret_cast<const float2*>(so + lp);
                *reinterpret_cast<float2*>(so + lp) = make_float2(old.x + r0, old.y + r1);
            }
        }
    }
}

// ---------------------------------------------------------------------------
// PinSage + final head: per position (b,l)
// ---------------------------------------------------------------------------
__global__ void __launch_bounds__(128) k_final(const float* __restrict__ n1w,
                                               const float* __restrict__ n1b,
                                               const float* __restrict__ n2w,
                                               const float* __restrict__ n2b,
                                               const float* __restrict__ upw,
                                               const float* __restrict__ upb,
                                               const float* __restrict__ fw,
                                               const float* __restrict__ fb,
                                               float* __restrict__ out) {
    __shared__ float s_n1w[768], s_n2w[768], s_n1b[48], s_n2b[48];
    __shared__ float s_upw[6144], s_upb[192], s_fw[64], s_fb;
    int tid = threadIdx.x;
    for (int idx = tid; idx < 768; idx += 128) { s_n1w[idx] = n1w[idx]; s_n2w[idx] = n2w[idx]; }
    for (int idx = tid; idx < 6144; idx += 128) s_upw[idx] = upw[idx];
    if (tid < 48) { s_n1b[tid] = n1b[tid]; s_n2b[tid] = n2b[tid]; }
    for (int idx = tid; idx < 192; idx += 128) s_upb[idx] = upb[idx];
    if (tid < 64) s_fw[tid] = fw[tid];
    if (tid == 0) s_fb = fb[0];
    __syncthreads();

    int gi = blockIdx.x * 128 + tid;   // 0 .. B*L-1
    int b = gi >> 12, l = gi & 4095;

    float F[3][16];
#pragma unroll
    for (int s = 0; s < 3; s++) {
        const float* sk = g_SK + (s * 8 + b) * CH * LL;
#pragma unroll
        for (int c = 0; c < 16; c++) F[s][c] = fmaxf(sk[c * LL + l], 0.f);
    }

    float m[64];
#pragma unroll
    for (int o = 0; o < 64; o++) m[o] = 0.f;   // all relu outputs >= 0

#pragma unroll
    for (int s = 0; s < 3; s++) {
        int n1 = (s == 0) ? 1 : 0;
        int n2 = (s == 2) ? 1 : 2;
        float nb[16];
#pragma unroll
        for (int o = 0; o < 16; o++) {
            float a1 = s_n1b[s * 16 + o], a2 = s_n2b[s * 16 + o];
#pragma unroll
            for (int c = 0; c < 16; c++) {
                a1 = fmaf(s_n1w[(s * 16 + o) * 16 + c], F[n1][c], a1);
                a2 = fmaf(s_n2w[(s * 16 + o) * 16 + c], F[n2][c], a2);
            }
            nb[o] = fmaxf(fmaxf(a1, 0.f), fmaxf(a2, 0.f));
        }
#pragma unroll 8
        for (int o = 0; o < 64; o++) {
            const float* wr = s_upw + (s * 64 + o) * 32;
            float u = s_upb[s * 64 + o];
#pragma unroll
            for (int c = 0; c < 16; c++) u = fmaf(wr[c], F[s][c], u);
#pragma unroll
            for (int c = 0; c < 16; c++) u = fmaf(wr[16 + c], nb[c], u);
            m[o] = fmaxf(m[o], fmaxf(u, 0.f));
        }
    }
    float logit = s_fb;
#pragma unroll
    for (int o = 0; o < 64; o++) logit = fmaf(s_fw[o], m[o], logit);
    out[gi] = fmaf(tanhap(logit * 0.5f), 0.5f, 0.5f);
}

// ---------------------------------------------------------------------------
extern "C" void kernel_launch(void* const* d_in, const int* in_sizes, int n_in,
                              void* d_out, int out_size) {
    const float* xin  = (const float*)d_in[0];
    const float* c1fw = (const float*)d_in[1];
    const float* c1fb = (const float*)d_in[2];
    const float* c1pw = (const float*)d_in[3];
    const float* c1pb = (const float*)d_in[4];
    const float* cfw  = (const float*)d_in[5];
    const float* cfb  = (const float*)d_in[6];
    const float* cgw  = (const float*)d_in[7];
    const float* cgb  = (const float*)d_in[8];
    const float* c2w  = (const float*)d_in[9];
    const float* c2b  = (const float*)d_in[10];
    const float* n1w  = (const float*)d_in[11];
    const float* n1b  = (const float*)d_in[12];
    const float* n2w  = (const float*)d_in[13];
    const float* n2b  = (const float*)d_in[14];
    const float* upw  = (const float*)d_in[15];
    const float* upb  = (const float*)d_in[16];
    const float* fw   = (const float*)d_in[17];
    const float* fb   = (const float*)d_in[18];
    float* out = (float*)d_out;

    // Max dynamic smem (d=1024): 2640*4 + 32*TILE*4 + 16*(TILE+1024)*4 = 125248 B
    int maxsm = 2640 * 4 + GC * TILE * 4 + 16 * (TILE + 1024) * 4;
    cudaFuncSetAttribute(k_gate<true>,  cudaFuncAttributeMaxDynamicSharedMemorySize, maxsm);
    cudaFuncSetAttribute(k_gate<false>, cudaFuncAttributeMaxDynamicSharedMemorySize, maxsm);

    dim3 g1(LL / 512, RR), b1(128);
    dim3 g2(LL / TILE, RR), b2(128);

    for (int i = 0; i < 33; i++) {
        int d = 1 << (i % 11);
        if (i == 0) k_first<<<g1, b1>>>(xin, c1fw, c1fb);
        else        k_point<<<g1, b1>>>(c1pw, c1pb, i);

        int smb = 2640 * 4 + GC * TILE * 4 + 16 * (TILE + d) * 4;
        if (i == 0) k_gate<true ><<<g2, b2, smb>>>(cfw, cfb, cgw, cgb, c2w, c2b, i, d);
        else        k_gate<false><<<g2, b2, smb>>>(cfw, cfb, cgw, cgb, c2w, c2b, i, d);
    }
    k_final<<<(BB * LL) / 128, 128>>>(n1w, n1b, n2w, n2b, upw, upb, fw, fb, out);
}

// round 3
// speedup vs baseline: 2.3949x; 2.3949x over previous
#include <cuda_runtime.h>

// ---------------------------------------------------------------------------
// Fused per-stage kernel: pointwise conv (into smem windows) + dilated gated
// conv + 1x1 squeeze + residual + skip. 33 launches + 1 final head.
// fp32 with packed fma.rn.f32x2 and HW tanh.approx.
// ---------------------------------------------------------------------------

#define S3   3
#define BB   8
#define CH   16
#define GC   32
#define LL   4096
#define RR   24          // S3*BB rows
#define TILE 128
#define NTHR 256

typedef unsigned long long ull;

__device__ __forceinline__ ull pk(float a, float b) {
    ull r; asm("mov.b64 %0, {%1,%2};" : "=l"(r) : "f"(a), "f"(b)); return r;
}
__device__ __forceinline__ ull dup2(float a) {
    ull r; asm("mov.b64 %0, {%1,%1};" : "=l"(r) : "f"(a)); return r;
}
__device__ __forceinline__ void upk(ull v, float &a, float &b) {
    asm("mov.b64 {%0,%1}, %2;" : "=f"(a), "=f"(b) : "l"(v));
}
__device__ __forceinline__ ull f2fma(ull a, ull b, ull c) {
    ull r; asm("fma.rn.f32x2 %0, %1, %2, %3;" : "=l"(r) : "l"(a), "l"(b), "l"(c)); return r;
}
__device__ __forceinline__ float tanhap(float x) {
    float r; asm("tanh.approx.f32 %0, %1;" : "=f"(r) : "f"(x)); return r;
}
__device__ __forceinline__ float sigap(float x) {
    return fmaf(tanhap(x * 0.5f), 0.5f, 0.5f);
}

// Residual stream double buffer + skip accumulator, [row][c][l]
__device__ float g_XA[RR * CH * LL];
__device__ float g_XB[RR * CH * LL];
__device__ float g_SK[RR * CH * LL];

// Shared layout (float offsets)
#define O_WF 0
#define O_WG 1024
#define O_W2 2048
#define O_W1 2560
#define O_BF 2816
#define O_BG 2848
#define O_B2 2880
#define O_B1 2896
#define O_H  2912          // 3 windows x 16 ch x 128  = 6144
#define O_Z  9056          // 32 ch x 128              = 4096
#define SM_FLOATS 13152    // 52608 bytes

// ---------------------------------------------------------------------------
template <bool FIRST>
__global__ void __launch_bounds__(NTHR, 2) k_stage(
        const float* __restrict__ Xsrc, float* __restrict__ Xdst,
        const float* __restrict__ xin,
        const float* __restrict__ pw, const float* __restrict__ pb,
        const float* __restrict__ cfw, const float* __restrict__ cfb,
        const float* __restrict__ cgw, const float* __restrict__ cgb,
        const float* __restrict__ c2w, const float* __restrict__ c2b,
        int i, int d, int last) {
    extern __shared__ float sm[];
    int tid = threadIdx.x;
    int row = blockIdx.y, s = row >> 3, bb = row & 7;
    int t0 = blockIdx.x * TILE;
    int a = d >> 1;

    // ---- stage weights -> smem ----
    {
        int wb = s * 33 + i;
        const float* fsrc = cfw + wb * 1024;
        const float* gsrc = cgw + wb * 1024;
#pragma unroll
        for (int k = 0; k < 4; k++) {
            sm[O_WF + tid + k * 256] = fsrc[tid + k * 256];
            sm[O_WG + tid + k * 256] = gsrc[tid + k * 256];
        }
        const float* w2src = c2w + wb * 512;
        sm[O_W2 + tid] = w2src[tid];
        sm[O_W2 + 256 + tid] = w2src[256 + tid];
        if (FIRST) {
            if (tid < 16) { sm[O_W1 + tid] = pw[s * 16 + tid]; sm[O_B1 + tid] = pb[s * 16 + tid]; }
        } else {
            int pbase = (s * 32 + (i - 1));
            sm[O_W1 + tid] = pw[pbase * 256 + tid];
            if (tid < 16) sm[O_B1 + tid] = pb[pbase * 16 + tid];
        }
        if (tid < 32) { sm[O_BF + tid] = cfb[wb * 32 + tid]; sm[O_BG + tid] = cgb[wb * 32 + tid]; }
        if (tid < 16) sm[O_B2 + tid] = c2b[wb * 16 + tid];
    }
    __syncthreads();

    // ---- fused pointwise: h = relu(W1 x + b1) into 3 smem windows ----
    // window 0: left taps  [t0-a, t0-a+128)
    // window 1: right taps [t0+d-a, t0+d-a+128)
    // window 2: center     [t0, t0+128)
    if (tid < 192) {
        int w = tid >> 6;                 // 0..2
        int p = (tid & 63) * 2;           // even position in window
        int wstart = (w == 0) ? t0 - a : (w == 1) ? t0 + d - a : t0;
        int pos0 = wstart + p;
        bool in0 = (unsigned)pos0 < LL;
        bool in1 = (unsigned)(pos0 + 1) < LL;
        float* hdst = sm + O_H + w * 2048 + p;
        if (FIRST) {
            float x0 = in0 ? xin[(bb * LL + pos0) * 3 + s] : 0.f;
            float x1 = in1 ? xin[(bb * LL + pos0 + 1) * 3 + s] : 0.f;
            ull xa = pk(x0, x1);
#pragma unroll
            for (int o = 0; o < 16; o++) {
                ull r = f2fma(xa, dup2(sm[O_W1 + o]), dup2(sm[O_B1 + o]));
                float r0, r1; upk(r, r0, r1);
                hdst[o * 128]     = in0 ? fmaxf(r0, 0.f) : 0.f;
                hdst[o * 128 + 1] = in1 ? fmaxf(r1, 0.f) : 0.f;
            }
        } else {
            const float* Xr = Xsrc + row * CH * LL;
            ull xa[16];
#pragma unroll
            for (int c = 0; c < 16; c++) {
                float x0 = in0 ? Xr[c * LL + pos0] : 0.f;
                float x1 = in1 ? Xr[c * LL + pos0 + 1] : 0.f;
                xa[c] = pk(x0, x1);
            }
#pragma unroll
            for (int o = 0; o < 16; o++) {
                ull acc = dup2(sm[O_B1 + o]);
#pragma unroll
                for (int c = 0; c < 16; c++)
                    acc = f2fma(xa[c], dup2(sm[O_W1 + o * 16 + c]), acc);
                float r0, r1; upk(acc, r0, r1);
                hdst[o * 128]     = in0 ? fmaxf(r0, 0.f) : 0.f;
                hdst[o * 128 + 1] = in1 ? fmaxf(r1, 0.f) : 0.f;
            }
        }
    }
    __syncthreads();

    // ---- main dilated gated conv: 4 oc x 4 positions per thread ----
    int q = tid >> 5;          // warp id: oc block q*4 (main), oc pair q*2 (z2)
    int pg = tid & 31;         // pair group: pairs at pg*2 and pg*2+64
    int ocb = q * 4;
    int pbase = pg * 2;

    ull fA[4][2], gA[4][2];
#pragma unroll
    for (int ii = 0; ii < 4; ii++) {
        ull fb = dup2(sm[O_BF + ocb + ii]), gb = dup2(sm[O_BG + ocb + ii]);
        fA[ii][0] = fb; fA[ii][1] = fb;
        gA[ii][0] = gb; gA[ii][1] = gb;
    }
#pragma unroll
    for (int c = 0; c < 16; c++) {
        const float* h0 = sm + O_H + c * 128 + pbase;
        const float* h1 = h0 + 2048;
        float2 a0 = *(const float2*)h0;
        float2 a1 = *(const float2*)(h0 + 64);
        float2 b0 = *(const float2*)h1;
        float2 b1 = *(const float2*)(h1 + 64);
        ull hl0 = pk(a0.x, a0.y), hl1 = pk(a1.x, a1.y);
        ull hr0 = pk(b0.x, b0.y), hr1 = pk(b1.x, b1.y);
#pragma unroll
        for (int ii = 0; ii < 4; ii++) {
            int wo = ((ocb + ii) * 16 + c) * 2;
            ull wf0 = dup2(sm[O_WF + wo]), wf1 = dup2(sm[O_WF + wo + 1]);
            ull wg0 = dup2(sm[O_WG + wo]), wg1 = dup2(sm[O_WG + wo + 1]);
            fA[ii][0] = f2fma(hl0, wf0, fA[ii][0]);
            fA[ii][0] = f2fma(hr0, wf1, fA[ii][0]);
            fA[ii][1] = f2fma(hl1, wf0, fA[ii][1]);
            fA[ii][1] = f2fma(hr1, wf1, fA[ii][1]);
            gA[ii][0] = f2fma(hl0, wg0, gA[ii][0]);
            gA[ii][0] = f2fma(hr0, wg1, gA[ii][0]);
            gA[ii][1] = f2fma(hl1, wg0, gA[ii][1]);
            gA[ii][1] = f2fma(hr1, wg1, gA[ii][1]);
        }
    }
    // activations -> z smem
#pragma unroll
    for (int ii = 0; ii < 4; ii++) {
        float* zp = sm + O_Z + (ocb + ii) * 128 + pbase;
#pragma unroll
        for (int j = 0; j < 2; j++) {
            float f0, f1, g0, g1;
            upk(fA[ii][j], f0, f1); upk(gA[ii][j], g0, g1);
            *(float2*)(zp + 64 * j) =
                make_float2(tanhap(f0) * sigap(g0), tanhap(f1) * sigap(g1));
        }
    }
    __syncthreads();

    // ---- z2 = relu(W2 z + b2); X = h + z2; SK += z2 ----
    int o0 = q * 2;
    ull acc[2][2];
#pragma unroll
    for (int oi = 0; oi < 2; oi++) {
        ull bv = dup2(sm[O_B2 + o0 + oi]);
        acc[oi][0] = bv; acc[oi][1] = bv;
    }
#pragma unroll 8
    for (int k = 0; k < 32; k++) {
        ull w0 = dup2(sm[O_W2 + o0 * 32 + k]);
        ull w1 = dup2(sm[O_W2 + o0 * 32 + 32 + k]);
        const float* zp = sm + O_Z + k * 128 + pbase;
        float2 z0 = *(const float2*)zp;
        float2 z1 = *(const float2*)(zp + 64);
        ull zz0 = pk(z0.x, z0.y), zz1 = pk(z1.x, z1.y);
        acc[0][0] = f2fma(zz0, w0, acc[0][0]);
        acc[0][1] = f2fma(zz1, w0, acc[0][1]);
        acc[1][0] = f2fma(zz0, w1, acc[1][0]);
        acc[1][1] = f2fma(zz1, w1, acc[1][1]);
    }
    float* SKg = g_SK + row * CH * LL;
#pragma unroll
    for (int oi = 0; oi < 2; oi++) {
        int o = o0 + oi;
        const float* hc = sm + O_H + 4096 + o * 128 + pbase;
        float* so = SKg + o * LL + t0 + pbase;
#pragma unroll
        for (int j = 0; j < 2; j++) {
            float r0, r1; upk(acc[oi][j], r0, r1);
            r0 = fmaxf(r0, 0.f); r1 = fmaxf(r1, 0.f);
            float2 hv = *(const float2*)(hc + 64 * j);
            if (!last)
                *(float2*)(Xdst + (row * CH + o) * LL + t0 + pbase + 64 * j) =
                    make_float2(hv.x + r0, hv.y + r1);
            if (FIRST) {
                *(float2*)(so + 64 * j) = make_float2(r0, r1);
            } else {
                float2 old = *(const float2*)(so + 64 * j);
                *(float2*)(so + 64 * j) = make_float2(old.x + r0, old.y + r1);
            }
        }
    }
}

// ---------------------------------------------------------------------------
// PinSage + final head (per position)
// ---------------------------------------------------------------------------
__global__ void __launch_bounds__(128) k_final(const float* __restrict__ n1w,
                                               const float* __restrict__ n1b,
                                               const float* __restrict__ n2w,
                                               const float* __restrict__ n2b,
                                               const float* __restrict__ upw,
                                               const float* __restrict__ upb,
                                               const float* __restrict__ fw,
                                               const float* __restrict__ fb,
                                               float* __restrict__ out) {
    __shared__ float s_n1w[768], s_n2w[768], s_n1b[48], s_n2b[48];
    __shared__ float s_upw[6144], s_upb[192], s_fw[64], s_fb;
    int tid = threadIdx.x;
    for (int idx = tid; idx < 768; idx += 128) { s_n1w[idx] = n1w[idx]; s_n2w[idx] = n2w[idx]; }
    for (int idx = tid; idx < 6144; idx += 128) s_upw[idx] = upw[idx];
    if (tid < 48) { s_n1b[tid] = n1b[tid]; s_n2b[tid] = n2b[tid]; }
    for (int idx = tid; idx < 192; idx += 128) s_upb[idx] = upb[idx];
    if (tid < 64) s_fw[tid] = fw[tid];
    if (tid == 0) s_fb = fb[0];
    __syncthreads();

    int gi = blockIdx.x * 128 + tid;
    int b = gi >> 12, l = gi & 4095;

    float F[3][16];
#pragma unroll
    for (int s = 0; s < 3; s++) {
        const float* sk = g_SK + (s * 8 + b) * CH * LL;
#pragma unroll
        for (int c = 0; c < 16; c++) F[s][c] = fmaxf(sk[c * LL + l], 0.f);
    }

    float m[64];
#pragma unroll
    for (int o = 0; o < 64; o++) m[o] = 0.f;

#pragma unroll
    for (int s = 0; s < 3; s++) {
        int n1 = (s == 0) ? 1 : 0;
        int n2 = (s == 2) ? 1 : 2;
        float nb[16];
#pragma unroll
        for (int o = 0; o < 16; o++) {
            float a1 = s_n1b[s * 16 + o], a2 = s_n2b[s * 16 + o];
#pragma unroll
            for (int c = 0; c < 16; c++) {
                a1 = fmaf(s_n1w[(s * 16 + o) * 16 + c], F[n1][c], a1);
                a2 = fmaf(s_n2w[(s * 16 + o) * 16 + c], F[n2][c], a2);
            }
            nb[o] = fmaxf(fmaxf(a1, 0.f), fmaxf(a2, 0.f));
        }
#pragma unroll 8
        for (int o = 0; o < 64; o++) {
            const float* wr = s_upw + (s * 64 + o) * 32;
            float u = s_upb[s * 64 + o];
#pragma unroll
            for (int c = 0; c < 16; c++) u = fmaf(wr[c], F[s][c], u);
#pragma unroll
            for (int c = 0; c < 16; c++) u = fmaf(wr[16 + c], nb[c], u);
            m[o] = fmaxf(m[o], fmaxf(u, 0.f));
        }
    }
    float logit = s_fb;
#pragma unroll
    for (int o = 0; o < 64; o++) logit = fmaf(s_fw[o], m[o], logit);
    out[gi] = fmaf(tanhap(logit * 0.5f), 0.5f, 0.5f);
}

// ---------------------------------------------------------------------------
extern "C" void kernel_launch(void* const* d_in, const int* in_sizes, int n_in,
                              void* d_out, int out_size) {
    const float* xin  = (const float*)d_in[0];
    const float* c1fw = (const float*)d_in[1];
    const float* c1fb = (const float*)d_in[2];
    const float* c1pw = (const float*)d_in[3];
    const float* c1pb = (const float*)d_in[4];
    const float* cfw  = (const float*)d_in[5];
    const float* cfb  = (const float*)d_in[6];
    const float* cgw  = (const float*)d_in[7];
    const float* cgb  = (const float*)d_in[8];
    const float* c2w  = (const float*)d_in[9];
    const float* c2b  = (const float*)d_in[10];
    const float* n1w  = (const float*)d_in[11];
    const float* n1b  = (const float*)d_in[12];
    const float* n2w  = (const float*)d_in[13];
    const float* n2b  = (const float*)d_in[14];
    const float* upw  = (const float*)d_in[15];
    const float* upb  = (const float*)d_in[16];
    const float* fw   = (const float*)d_in[17];
    const float* fb   = (const float*)d_in[18];
    float* out = (float*)d_out;

    static int inited = 0;
    const int smb = SM_FLOATS * 4;
    if (!inited) {
        cudaFuncSetAttribute(k_stage<true>,  cudaFuncAttributeMaxDynamicSharedMemorySize, smb);
        cudaFuncSetAttribute(k_stage<false>, cudaFuncAttributeMaxDynamicSharedMemorySize, smb);
        inited = 1;
    }

    float* xa; float* xb;
    cudaGetSymbolAddress((void**)&xa, g_XA);
    cudaGetSymbolAddress((void**)&xb, g_XB);
    float* bufs[2] = {xa, xb};

    dim3 gs(LL / TILE, RR), bs(NTHR);
    for (int i = 0; i < 33; i++) {
        int d = 1 << (i % 11);
        int last = (i == 32);
        float* dst = bufs[i & 1];
        const float* src = bufs[(i + 1) & 1];
        if (i == 0)
            k_stage<true><<<gs, bs, smb>>>(nullptr, dst, xin, c1fw, c1fb,
                                           cfw, cfb, cgw, cgb, c2w, c2b, i, d, last);
        else
            k_stage<false><<<gs, bs, smb>>>(src, dst, xin, c1pw, c1pb,
                                            cfw, cfb, cgw, cgb, c2w, c2b, i, d, last);
    }
    k_final<<<(BB * LL) / 128, 128>>>(n1w, n1b, n2w, n2b, upw, upb, fw, fb, out);
}